// round 1
// baseline (speedup 1.0000x reference)
#include <cuda_runtime.h>
#include <cuda_bf16.h>
#include <cstdint>

#define BB   8
#define NCAM 6
#define DD   41
#define FHH  8
#define FWW  22
#define CC   64
#define NXY  200
#define PTS_PER_CAM (DD*FHH*FWW)          /* 7216 */
#define NPTS (BB*NCAM*PTS_PER_CAM)        /* 346368 */
#define GRID_CELLS (BB*NXY*NXY)           /* 320000 */

// Scratch: channel-last voxel grid [B,200,200,C]  (81.92 MB, static device alloc)
__device__ float g_scratch[(size_t)GRID_CELLS * CC];
// Per-camera fused params: inv(post_rots)[9], post_trans[3], combine[9], trans[3]
__device__ float g_cam[BB * NCAM][24];
// Per-point voxel index (-1 if dropped)
__device__ int g_vox[NPTS];

// ---------------------------------------------------------------------------
// 3x3 inverse via adjugate in double (correctly-rounded vs reference's f32 LU)
__device__ __forceinline__ void inv3(const float* a, double* inv) {
    double a00=a[0],a01=a[1],a02=a[2];
    double a10=a[3],a11=a[4],a12=a[5];
    double a20=a[6],a21=a[7],a22=a[8];
    double c00 = a11*a22 - a12*a21;
    double c01 = a12*a20 - a10*a22;
    double c02 = a10*a21 - a11*a20;
    double det = a00*c00 + a01*c01 + a02*c02;
    double id  = 1.0/det;
    inv[0] = c00*id;
    inv[1] = (a02*a21 - a01*a22)*id;
    inv[2] = (a01*a12 - a02*a11)*id;
    inv[3] = c01*id;
    inv[4] = (a00*a22 - a02*a20)*id;
    inv[5] = (a02*a10 - a00*a12)*id;
    inv[6] = c02*id;
    inv[7] = (a01*a20 - a00*a21)*id;
    inv[8] = (a00*a11 - a01*a10)*id;
}

__global__ void cam_setup(const float* __restrict__ rots,
                          const float* __restrict__ trans,
                          const float* __restrict__ intrins,
                          const float* __restrict__ post_rots,
                          const float* __restrict__ post_trans) {
    int i = threadIdx.x;
    if (i >= BB * NCAM) return;
    double ipr[9], ik[9];
    inv3(post_rots + i*9, ipr);
    inv3(intrins   + i*9, ik);
    float* cp = g_cam[i];
    #pragma unroll
    for (int k = 0; k < 9; k++) cp[k] = (float)ipr[k];
    cp[9]  = post_trans[i*3 + 0];
    cp[10] = post_trans[i*3 + 1];
    cp[11] = post_trans[i*3 + 2];
    const float* rt = rots + i*9;
    #pragma unroll
    for (int r = 0; r < 3; r++)
        #pragma unroll
        for (int c = 0; c < 3; c++) {
            double s = (double)rt[r*3+0]*ik[0*3+c]
                     + (double)rt[r*3+1]*ik[1*3+c]
                     + (double)rt[r*3+2]*ik[2*3+c];
            cp[12 + r*3 + c] = (float)s;
        }
    cp[21] = trans[i*3 + 0];
    cp[22] = trans[i*3 + 1];
    cp[23] = trans[i*3 + 2];
}

// ---------------------------------------------------------------------------
// Per-point geometry -> voxel index. f32 ops mirror the reference chain.
__global__ void voxelize() {
    int idx = blockIdx.x * blockDim.x + threadIdx.x;
    if (idx >= NPTS) return;
    int cam = idx / PTS_PER_CAM;
    int r   = idx - cam * PTS_PER_CAM;
    int d   = r / (FHH * FWW);
    int r2  = r - d * (FHH * FWW);
    int h   = r2 / FWW;
    int w   = r2 - h * FWW;

    const float* cp = g_cam[cam];
    const float XSTEP = 351.0f / 21.0f;   // matches f32 linspace step
    const float YSTEP = 127.0f / 7.0f;
    float fx = (float)w * XSTEP;
    float fy = (float)h * YSTEP;
    float fz = 4.0f + (float)d;

    float px = fx - cp[9];
    float py = fy - cp[10];
    float pz = fz - cp[11];
    // q = inv(post_rots) @ p   (fma chain, k-order accumulation)
    float q0 = fmaf(cp[2], pz, fmaf(cp[1], py, cp[0]*px));
    float q1 = fmaf(cp[5], pz, fmaf(cp[4], py, cp[3]*px));
    float q2 = fmaf(cp[8], pz, fmaf(cp[7], py, cp[6]*px));
    // unproject: (u*d, v*d, d)
    float r0 = q0 * q2;
    float r1 = q1 * q2;
    float r2v = q2;
    // geom = combine @ r + trans
    float g0 = fmaf(cp[14], r2v, fmaf(cp[13], r1, cp[12]*r0)) + cp[21];
    float g1 = fmaf(cp[17], r2v, fmaf(cp[16], r1, cp[15]*r0)) + cp[22];
    float g2 = fmaf(cp[20], r2v, fmaf(cp[19], r1, cp[18]*r0)) + cp[23];

    // quantize: (geom - (BX - DX/2)) / DX, truncate toward zero
    float v0 = (g0 + 50.0f) / 0.5f;
    float v1 = (g1 + 50.0f) / 0.5f;
    float v2 = (g2 + 10.0f) / 20.0f;
    int i0 = (int)v0;
    int i1 = (int)v1;
    int i2 = (int)v2;

    int vox = -1;
    if (i0 >= 0 && i0 < NXY && i1 >= 0 && i1 < NXY && i2 == 0) {
        int b = cam / NCAM;
        vox = (b * NXY + i0) * NXY + i1;
    }
    g_vox[idx] = vox;
}

// ---------------------------------------------------------------------------
__global__ void zero_scratch() {
    int i = blockIdx.x * blockDim.x + threadIdx.x;
    const int n4 = GRID_CELLS * CC / 4;   // 5,120,000 float4
    if (i < n4) {
        float4 z = make_float4(0.f, 0.f, 0.f, 0.f);
        reinterpret_cast<float4*>(g_scratch)[i] = z;
    }
}

// ---------------------------------------------------------------------------
// Scatter-add: 16 threads per point, float4 per thread, vector red.
__global__ void scatter(const float* __restrict__ x_feats) {
    int gid = blockIdx.x * blockDim.x + threadIdx.x;
    if (gid >= NPTS * 16) return;
    int point = gid >> 4;
    int c4    = gid & 15;
    int vox   = g_vox[point];
    if (vox < 0) return;
    float4 f = reinterpret_cast<const float4*>(x_feats)[gid];
    float* dst = g_scratch + (size_t)vox * CC + c4 * 4;
    asm volatile("red.global.add.v4.f32 [%0], {%1,%2,%3,%4};"
                 :: "l"(dst), "f"(f.x), "f"(f.y), "f"(f.z), "f"(f.w)
                 : "memory");
}

// ---------------------------------------------------------------------------
// Transpose [B,200(x),200(y),C] -> out [B,C,200(x),200(y)]
__global__ void transpose_out(float* __restrict__ out) {
    __shared__ float tile[32][33];
    int bx = blockIdx.z;              // b*200 + x
    int c0 = blockIdx.y * 32;
    int y0 = blockIdx.x * 32;
    const float* src = g_scratch + (size_t)bx * NXY * CC;  // rows of 64 ch per y
    #pragma unroll
    for (int rr = 0; rr < 32; rr += 8) {
        int y = y0 + threadIdx.y + rr;
        if (y < NXY)
            tile[threadIdx.y + rr][threadIdx.x] = src[y * CC + c0 + threadIdx.x];
    }
    __syncthreads();
    int b = bx / NXY;
    int x = bx - b * NXY;
    #pragma unroll
    for (int rr = 0; rr < 32; rr += 8) {
        int c = c0 + threadIdx.y + rr;
        int y = y0 + threadIdx.x;
        if (y < NXY)
            out[(((size_t)b * CC + c) * NXY + x) * NXY + y] = tile[threadIdx.x][threadIdx.y + rr];
    }
}

// ---------------------------------------------------------------------------
extern "C" void kernel_launch(void* const* d_in, const int* in_sizes, int n_in,
                              void* d_out, int out_size) {
    const float* x_feats    = (const float*)d_in[0];
    const float* rots       = (const float*)d_in[1];
    const float* trans      = (const float*)d_in[2];
    const float* intrins    = (const float*)d_in[3];
    const float* post_rots  = (const float*)d_in[4];
    const float* post_trans = (const float*)d_in[5];
    float* out = (float*)d_out;

    cam_setup<<<1, 64>>>(rots, trans, intrins, post_rots, post_trans);
    voxelize<<<(NPTS + 255) / 256, 256>>>();
    zero_scratch<<<(GRID_CELLS * CC / 4 + 255) / 256, 256>>>();
    scatter<<<(NPTS * 16 + 255) / 256, 256>>>(x_feats);
    transpose_out<<<dim3(7, 2, BB * NXY), dim3(32, 8)>>>(out);
}

// round 2
// speedup vs baseline: 1.0197x; 1.0197x over previous
#include <cuda_runtime.h>
#include <cuda_bf16.h>
#include <cstdint>

#define BB   8
#define NCAM 6
#define DD   41
#define FHH  8
#define FWW  22
#define CC   64
#define NXY  200
#define PTS_PER_CAM (DD*FHH*FWW)          /* 7216 */
#define NPTS (BB*NCAM*PTS_PER_CAM)        /* 346368 */
#define GRID_CELLS (BB*NXY*NXY)           /* 320000 */

// Scratch: channel-last voxel grid [B,200,200,C]  (81.92 MB, static device alloc)
// INVARIANT: all-zero at the start of every kernel_launch call. Static init
// zeroes it; transpose_out re-zeroes every touched cell after reading it.
__device__ float g_scratch[(size_t)GRID_CELLS * CC];
// Per-cell touched flag (zeroed each call by voxelize, set by scatter)
__device__ unsigned g_count[GRID_CELLS];
// Per-camera fused params: inv(post_rots)[9], post_trans[3], combine[9], trans[3]
__device__ float g_cam[BB * NCAM][24];
// Per-point voxel index (-1 if dropped)
__device__ int g_vox[NPTS];

// ---------------------------------------------------------------------------
// 3x3 inverse via adjugate in double (correctly-rounded vs reference's f32 LU)
__device__ __forceinline__ void inv3(const float* a, double* inv) {
    double a00=a[0],a01=a[1],a02=a[2];
    double a10=a[3],a11=a[4],a12=a[5];
    double a20=a[6],a21=a[7],a22=a[8];
    double c00 = a11*a22 - a12*a21;
    double c01 = a12*a20 - a10*a22;
    double c02 = a10*a21 - a11*a20;
    double det = a00*c00 + a01*c01 + a02*c02;
    double id  = 1.0/det;
    inv[0] = c00*id;
    inv[1] = (a02*a21 - a01*a22)*id;
    inv[2] = (a01*a12 - a02*a11)*id;
    inv[3] = c01*id;
    inv[4] = (a00*a22 - a02*a20)*id;
    inv[5] = (a02*a10 - a00*a12)*id;
    inv[6] = c02*id;
    inv[7] = (a01*a20 - a00*a21)*id;
    inv[8] = (a00*a11 - a01*a10)*id;
}

__global__ void cam_setup(const float* __restrict__ rots,
                          const float* __restrict__ trans,
                          const float* __restrict__ intrins,
                          const float* __restrict__ post_rots,
                          const float* __restrict__ post_trans) {
    int i = threadIdx.x;
    if (i >= BB * NCAM) return;
    double ipr[9], ik[9];
    inv3(post_rots + i*9, ipr);
    inv3(intrins   + i*9, ik);
    float* cp = g_cam[i];
    #pragma unroll
    for (int k = 0; k < 9; k++) cp[k] = (float)ipr[k];
    cp[9]  = post_trans[i*3 + 0];
    cp[10] = post_trans[i*3 + 1];
    cp[11] = post_trans[i*3 + 2];
    const float* rt = rots + i*9;
    #pragma unroll
    for (int r = 0; r < 3; r++)
        #pragma unroll
        for (int c = 0; c < 3; c++) {
            double s = (double)rt[r*3+0]*ik[0*3+c]
                     + (double)rt[r*3+1]*ik[1*3+c]
                     + (double)rt[r*3+2]*ik[2*3+c];
            cp[12 + r*3 + c] = (float)s;
        }
    cp[21] = trans[i*3 + 0];
    cp[22] = trans[i*3 + 1];
    cp[23] = trans[i*3 + 2];
}

// ---------------------------------------------------------------------------
// Per-point geometry -> voxel index. f32 ops mirror the reference chain.
// Also zeroes the per-cell touched flags (GRID_CELLS < NPTS threads).
__global__ void voxelize() {
    int idx = blockIdx.x * blockDim.x + threadIdx.x;
    if (idx >= NPTS) return;
    if (idx < GRID_CELLS) g_count[idx] = 0u;

    int cam = idx / PTS_PER_CAM;
    int r   = idx - cam * PTS_PER_CAM;
    int d   = r / (FHH * FWW);
    int r2  = r - d * (FHH * FWW);
    int h   = r2 / FWW;
    int w   = r2 - h * FWW;

    const float* cp = g_cam[cam];
    const float XSTEP = 351.0f / 21.0f;   // matches f32 linspace step
    const float YSTEP = 127.0f / 7.0f;
    float fx = (float)w * XSTEP;
    float fy = (float)h * YSTEP;
    float fz = 4.0f + (float)d;

    float px = fx - cp[9];
    float py = fy - cp[10];
    float pz = fz - cp[11];
    // q = inv(post_rots) @ p   (fma chain, k-order accumulation)
    float q0 = fmaf(cp[2], pz, fmaf(cp[1], py, cp[0]*px));
    float q1 = fmaf(cp[5], pz, fmaf(cp[4], py, cp[3]*px));
    float q2 = fmaf(cp[8], pz, fmaf(cp[7], py, cp[6]*px));
    // unproject: (u*d, v*d, d)
    float r0 = q0 * q2;
    float r1 = q1 * q2;
    float r2v = q2;
    // geom = combine @ r + trans
    float g0 = fmaf(cp[14], r2v, fmaf(cp[13], r1, cp[12]*r0)) + cp[21];
    float g1 = fmaf(cp[17], r2v, fmaf(cp[16], r1, cp[15]*r0)) + cp[22];
    float g2 = fmaf(cp[20], r2v, fmaf(cp[19], r1, cp[18]*r0)) + cp[23];

    // quantize: (geom - (BX - DX/2)) / DX, truncate toward zero
    float v0 = (g0 + 50.0f) / 0.5f;
    float v1 = (g1 + 50.0f) / 0.5f;
    float v2 = (g2 + 10.0f) / 20.0f;
    int i0 = (int)v0;
    int i1 = (int)v1;
    int i2 = (int)v2;

    int vox = -1;
    if (i0 >= 0 && i0 < NXY && i1 >= 0 && i1 < NXY && i2 == 0) {
        int b = cam / NCAM;
        vox = (b * NXY + i0) * NXY + i1;
    }
    g_vox[idx] = vox;
}

// ---------------------------------------------------------------------------
// Scatter-add: 16 threads per point, float4 per thread, vector red.
// Lane 0 of each point marks the cell as touched.
__global__ void scatter(const float* __restrict__ x_feats) {
    int gid = blockIdx.x * blockDim.x + threadIdx.x;
    if (gid >= NPTS * 16) return;
    int point = gid >> 4;
    int c4    = gid & 15;
    int vox   = g_vox[point];
    if (vox < 0) return;
    if (c4 == 0) g_count[vox] = 1u;   // benign race: all writers store 1
    float4 f = reinterpret_cast<const float4*>(x_feats)[gid];
    float* dst = g_scratch + (size_t)vox * CC + c4 * 4;
    asm volatile("red.global.add.v4.f32 [%0], {%1,%2,%3,%4};"
                 :: "l"(dst), "f"(f.x), "f"(f.y), "f"(f.z), "f"(f.w)
                 : "memory");
}

// ---------------------------------------------------------------------------
// Transpose [B,200(x),200(y),C] -> out [B,C,200(x),200(y)].
// Skips reading scratch for tiles whose 32 cells are all untouched; re-zeroes
// scratch cells it does read (maintains the all-zero invariant for next call).
__global__ void transpose_out(float* __restrict__ out) {
    __shared__ float tile[32][65];
    __shared__ int s_touched;
    int tid = threadIdx.x;               // 256 threads
    int bx  = blockIdx.y;                // b*200 + x
    int y0  = blockIdx.x * 32;
    int b = bx / NXY;
    int x = bx - b * NXY;
    int cellbase = bx * NXY;

    if (tid == 0) s_touched = 0;
    __syncthreads();
    if (tid < 32) {
        int y = y0 + tid;
        unsigned c = (y < NXY) ? g_count[cellbase + y] : 0u;
        unsigned m = __ballot_sync(0xffffffffu, c != 0u);
        if (tid == 0) s_touched = (m != 0u);
    }
    __syncthreads();

    int yl  = tid & 31;
    int clo = tid >> 5;                  // 0..7
    int yg  = y0 + yl;

    if (s_touched) {
        // Load 32y x 64c tile as float4 + re-zero scratch behind the read.
        float4* srcbase = reinterpret_cast<float4*>(g_scratch + (size_t)cellbase * CC);
        int c4  = tid & 15;
        int ylo = tid >> 4;              // 0..15
        #pragma unroll
        for (int i = 0; i < 2; i++) {
            int y = ylo + 16 * i;
            if (y0 + y < NXY) {
                float4 v = srcbase[(size_t)(y0 + y) * 16 + c4];
                tile[y][c4 * 4 + 0] = v.x;
                tile[y][c4 * 4 + 1] = v.y;
                tile[y][c4 * 4 + 2] = v.z;
                tile[y][c4 * 4 + 3] = v.w;
                srcbase[(size_t)(y0 + y) * 16 + c4] = make_float4(0.f, 0.f, 0.f, 0.f);
            }
        }
        __syncthreads();
        if (yg < NXY) {
            #pragma unroll
            for (int i = 0; i < 8; i++) {
                int c = clo + 8 * i;
                out[(((size_t)b * CC + c) * NXY + x) * NXY + yg] = tile[yl][c];
            }
        }
    } else {
        if (yg < NXY) {
            #pragma unroll
            for (int i = 0; i < 8; i++) {
                int c = clo + 8 * i;
                out[(((size_t)b * CC + c) * NXY + x) * NXY + yg] = 0.f;
            }
        }
    }
}

// ---------------------------------------------------------------------------
extern "C" void kernel_launch(void* const* d_in, const int* in_sizes, int n_in,
                              void* d_out, int out_size) {
    const float* x_feats    = (const float*)d_in[0];
    const float* rots       = (const float*)d_in[1];
    const float* trans      = (const float*)d_in[2];
    const float* intrins    = (const float*)d_in[3];
    const float* post_rots  = (const float*)d_in[4];
    const float* post_trans = (const float*)d_in[5];
    float* out = (float*)d_out;

    cam_setup<<<1, 64>>>(rots, trans, intrins, post_rots, post_trans);
    voxelize<<<(NPTS + 255) / 256, 256>>>();
    scatter<<<(NPTS * 16 + 255) / 256, 256>>>(x_feats);
    transpose_out<<<dim3(7, BB * NXY), 256>>>(out);
}

// round 3
// speedup vs baseline: 1.3158x; 1.2903x over previous
#include <cuda_runtime.h>
#include <cuda_bf16.h>
#include <cstdint>

#define BB   8
#define NCAM 6
#define DD   41
#define FHH  8
#define FWW  22
#define CC   64
#define NXY  200
#define PTS_PER_CAM (DD*FHH*FWW)          /* 7216 */
#define NPTS (BB*NCAM*PTS_PER_CAM)        /* 346368 */
#define GRID_CELLS (BB*NXY*NXY)           /* 320000 */

// Scratch: channel-last voxel grid [B,200,200,C]  (81.92 MB, static device alloc)
// INVARIANT: all-zero at the start of every kernel_launch call. Static init
// zeroes it; transpose_out re-zeroes every touched cell after reading it.
__device__ float g_scratch[(size_t)GRID_CELLS * CC];
// Per-cell touched flag. INVARIANT: all-zero at call start; scatter sets,
// transpose_out reads + clears.
__device__ unsigned g_count[GRID_CELLS];
// Per-camera fused params: inv(post_rots)[9], post_trans[3], combine[9], trans[3]
__device__ float g_cam[BB * NCAM][24];

// ---------------------------------------------------------------------------
// 3x3 inverse via adjugate in double (correctly-rounded vs reference's f32 LU)
__device__ __forceinline__ void inv3(const float* a, double* inv) {
    double a00=a[0],a01=a[1],a02=a[2];
    double a10=a[3],a11=a[4],a12=a[5];
    double a20=a[6],a21=a[7],a22=a[8];
    double c00 = a11*a22 - a12*a21;
    double c01 = a12*a20 - a10*a22;
    double c02 = a10*a21 - a11*a20;
    double det = a00*c00 + a01*c01 + a02*c02;
    double id  = 1.0/det;
    inv[0] = c00*id;
    inv[1] = (a02*a21 - a01*a22)*id;
    inv[2] = (a01*a12 - a02*a11)*id;
    inv[3] = c01*id;
    inv[4] = (a00*a22 - a02*a20)*id;
    inv[5] = (a02*a10 - a00*a12)*id;
    inv[6] = c02*id;
    inv[7] = (a01*a20 - a00*a21)*id;
    inv[8] = (a00*a11 - a01*a10)*id;
}

__global__ void cam_setup(const float* __restrict__ rots,
                          const float* __restrict__ trans,
                          const float* __restrict__ intrins,
                          const float* __restrict__ post_rots,
                          const float* __restrict__ post_trans) {
    int i = threadIdx.x;
    if (i >= BB * NCAM) return;
    double ipr[9], ik[9];
    inv3(post_rots + i*9, ipr);
    inv3(intrins   + i*9, ik);
    float* cp = g_cam[i];
    #pragma unroll
    for (int k = 0; k < 9; k++) cp[k] = (float)ipr[k];
    cp[9]  = post_trans[i*3 + 0];
    cp[10] = post_trans[i*3 + 1];
    cp[11] = post_trans[i*3 + 2];
    const float* rt = rots + i*9;
    #pragma unroll
    for (int r = 0; r < 3; r++)
        #pragma unroll
        for (int c = 0; c < 3; c++) {
            double s = (double)rt[r*3+0]*ik[0*3+c]
                     + (double)rt[r*3+1]*ik[1*3+c]
                     + (double)rt[r*3+2]*ik[2*3+c];
            cp[12 + r*3 + c] = (float)s;
        }
    cp[21] = trans[i*3 + 0];
    cp[22] = trans[i*3 + 1];
    cp[23] = trans[i*3 + 2];
}

// ---------------------------------------------------------------------------
// Fused voxelize + scatter-add. 16 threads per point (one float4 of channels
// each). All 16 lanes redundantly compute the point's voxel index — this
// costs the same warp issue as computing it on one lane (SIMT), and removes
// the separate voxelize kernel plus the g_vox round-trip.
__global__ void scatter(const float* __restrict__ x_feats) {
    int gid = blockIdx.x * blockDim.x + threadIdx.x;
    if (gid >= NPTS * 16) return;
    int point = gid >> 4;
    int c4    = gid & 15;

    int cam = point / PTS_PER_CAM;
    int r   = point - cam * PTS_PER_CAM;
    int d   = r / (FHH * FWW);
    int r2  = r - d * (FHH * FWW);
    int h   = r2 / FWW;
    int w   = r2 - h * FWW;

    const float* cp = g_cam[cam];
    const float XSTEP = 351.0f / 21.0f;   // matches f32 linspace step
    const float YSTEP = 127.0f / 7.0f;
    float fx = (float)w * XSTEP;
    float fy = (float)h * YSTEP;
    float fz = 4.0f + (float)d;

    float px = fx - cp[9];
    float py = fy - cp[10];
    float pz = fz - cp[11];
    // q = inv(post_rots) @ p   (fma chain, k-order accumulation)
    float q0 = fmaf(cp[2], pz, fmaf(cp[1], py, cp[0]*px));
    float q1 = fmaf(cp[5], pz, fmaf(cp[4], py, cp[3]*px));
    float q2 = fmaf(cp[8], pz, fmaf(cp[7], py, cp[6]*px));
    // unproject: (u*d, v*d, d)
    float r0 = q0 * q2;
    float r1 = q1 * q2;
    float r2v = q2;
    // geom = combine @ r + trans
    float g0 = fmaf(cp[14], r2v, fmaf(cp[13], r1, cp[12]*r0)) + cp[21];
    float g1 = fmaf(cp[17], r2v, fmaf(cp[16], r1, cp[15]*r0)) + cp[22];
    float g2 = fmaf(cp[20], r2v, fmaf(cp[19], r1, cp[18]*r0)) + cp[23];

    // quantize: (geom - (BX - DX/2)) / DX, truncate toward zero
    float v0 = (g0 + 50.0f) / 0.5f;
    float v1 = (g1 + 50.0f) / 0.5f;
    float v2 = (g2 + 10.0f) / 20.0f;
    int i0 = (int)v0;
    int i1 = (int)v1;
    int i2 = (int)v2;

    if (i0 < 0 || i0 >= NXY || i1 < 0 || i1 >= NXY || i2 != 0) return;
    int b   = cam / NCAM;
    int vox = (b * NXY + i0) * NXY + i1;

    if (c4 == 0) g_count[vox] = 1u;   // benign race: all writers store 1
    float4 f = reinterpret_cast<const float4*>(x_feats)[gid];
    float* dst = g_scratch + (size_t)vox * CC + c4 * 4;
    asm volatile("red.global.add.v4.f32 [%0], {%1,%2,%3,%4};"
                 :: "l"(dst), "f"(f.x), "f"(f.y), "f"(f.z), "f"(f.w)
                 : "memory");
}

// ---------------------------------------------------------------------------
// Transpose [B,200(x),200(y),C] -> out [B,C,200(x),200(y)].
// Per-cell skip: untouched cells contribute constant zero without any scratch
// read or re-zero. Touched cells are read once and zeroed behind the read
// (maintains the all-zero invariant). g_count is always cleared.
// Output written as float4 (STG.128), 4 coalesced 128B segments per warp store.
__global__ void transpose_out(float* __restrict__ out) {
    __shared__ float tile[32][65];
    __shared__ unsigned s_flag[32];
    __shared__ int s_touched;
    int tid = threadIdx.x;               // 256 threads
    int bx  = blockIdx.y;                // b*200 + x
    int y0  = blockIdx.x * 32;
    int b = bx / NXY;
    int x = bx - b * NXY;
    int cellbase = bx * NXY;

    if (tid < 32) {
        int y = y0 + tid;
        unsigned f = 0u;
        if (y < NXY) {
            f = g_count[cellbase + y];
            if (f) g_count[cellbase + y] = 0u;
        }
        s_flag[tid] = f;
        unsigned m = __ballot_sync(0xffffffffu, f != 0u);
        if (tid == 0) s_touched = (m != 0u);
    }
    __syncthreads();

    int lane = tid & 31;
    int warp = tid >> 5;                 // 0..7
    int cgrp = lane >> 3;                // 0..3
    int yseg = lane & 7;                 // 0..7
    int yg4  = y0 + yseg * 4;            // float4-aligned y

    if (s_touched) {
        // Load 32y x 64c tile as float4; skip + keep-zero for untouched cells.
        float4* srcbase = reinterpret_cast<float4*>(g_scratch + (size_t)cellbase * CC);
        int c4  = tid & 15;
        int ylo = tid >> 4;              // 0..15
        #pragma unroll
        for (int i = 0; i < 2; i++) {
            int y  = ylo + 16 * i;
            int yg = y0 + y;
            if (yg < NXY) {
                float4 v = make_float4(0.f, 0.f, 0.f, 0.f);
                if (s_flag[y]) {
                    v = srcbase[(size_t)yg * 16 + c4];
                    srcbase[(size_t)yg * 16 + c4] = make_float4(0.f, 0.f, 0.f, 0.f);
                }
                tile[y][c4 * 4 + 0] = v.x;
                tile[y][c4 * 4 + 1] = v.y;
                tile[y][c4 * 4 + 2] = v.z;
                tile[y][c4 * 4 + 3] = v.w;
            }
        }
        __syncthreads();
        if (yg4 < NXY) {
            #pragma unroll
            for (int j = 0; j < 2; j++) {
                int c = warp * 4 + cgrp + j * 32;
                int yl = yseg * 4;
                float4 v;
                v.x = tile[yl + 0][c];
                v.y = tile[yl + 1][c];
                v.z = tile[yl + 2][c];
                v.w = tile[yl + 3][c];
                size_t o4 = ((((size_t)b * CC + c) * NXY + x) * NXY + yg4) >> 2;
                reinterpret_cast<float4*>(out)[o4] = v;
            }
        }
    } else {
        if (yg4 < NXY) {
            float4 z = make_float4(0.f, 0.f, 0.f, 0.f);
            #pragma unroll
            for (int j = 0; j < 2; j++) {
                int c = warp * 4 + cgrp + j * 32;
                size_t o4 = ((((size_t)b * CC + c) * NXY + x) * NXY + yg4) >> 2;
                reinterpret_cast<float4*>(out)[o4] = z;
            }
        }
    }
}

// ---------------------------------------------------------------------------
extern "C" void kernel_launch(void* const* d_in, const int* in_sizes, int n_in,
                              void* d_out, int out_size) {
    const float* x_feats    = (const float*)d_in[0];
    const float* rots       = (const float*)d_in[1];
    const float* trans      = (const float*)d_in[2];
    const float* intrins    = (const float*)d_in[3];
    const float* post_rots  = (const float*)d_in[4];
    const float* post_trans = (const float*)d_in[5];
    float* out = (float*)d_out;

    cam_setup<<<1, 64>>>(rots, trans, intrins, post_rots, post_trans);
    scatter<<<(NPTS * 16 + 255) / 256, 256>>>(x_feats);
    transpose_out<<<dim3(7, BB * NXY), 256>>>(out);
}